// round 1
// baseline (speedup 1.0000x reference)
#include <cuda_runtime.h>
#include <math.h>

#define T_TOK 2048
#define H_DIM 2048
#define I_DIM 768
#define E_NUM 32
#define K_TOP 8
#define CAP   1024
#define A_TOTAL (T_TOK * K_TOP)

// ---------------- device scratch (static globals: no allocation) ----------------
__device__ float g_gate_wT[E_NUM * H_DIM];      // 256 KB, gate_w transposed [E][H]
__device__ int   g_cnt[E_NUM];
__device__ int   g_tok[E_NUM * CAP];            // source token id per (expert, slot)
__device__ int   g_aid[E_NUM * CAP];            // assignment id = t*8+k per (expert, slot)
__device__ float g_wgt[E_NUM * CAP];            // routing weight per (expert, slot)
__device__ float g_h[(size_t)E_NUM * CAP * I_DIM];   // 96 MB, silu(g)*u per slot
__device__ float g_y[(size_t)A_TOTAL * H_DIM];       // 128 MB, per-assignment output rows

// ---------------- prep: transpose gate_w, zero counters ----------------
__global__ void prep_kernel(const float* __restrict__ gate_w) {
    int i = blockIdx.x * 256 + threadIdx.x;       // 0 .. 65535
    if (i < E_NUM * H_DIM) {
        int e = i >> 11;                           // H_DIM = 2048
        int h = i & (H_DIM - 1);
        g_gate_wT[i] = gate_w[h * E_NUM + e];
    }
    if (i < E_NUM) g_cnt[i] = 0;
}

// ---------------- router: logits -> softmax -> top8 -> renorm -> assign ----------------
__global__ __launch_bounds__(256) void router_kernel(const float* __restrict__ x,
                                                     const float* __restrict__ gate_b) {
    __shared__ float xs[H_DIM];
    __shared__ float lg[E_NUM];
    const int t = blockIdx.x;
    const int tid = threadIdx.x;

    const float4* xr = (const float4*)(x + (size_t)t * H_DIM);
    for (int i = tid; i < H_DIM / 4; i += 256) ((float4*)xs)[i] = xr[i];
    __syncthreads();

    const int w = tid >> 5, lane = tid & 31;
#pragma unroll
    for (int ee = 0; ee < 4; ee++) {
        const int e = (w << 2) + ee;
        const float* gw = g_gate_wT + (size_t)e * H_DIM;
        float s = 0.f;
        for (int h = lane; h < H_DIM; h += 32) s += xs[h] * gw[h];
#pragma unroll
        for (int off = 16; off; off >>= 1) s += __shfl_xor_sync(0xffffffffu, s, off);
        if (lane == 0) lg[e] = s + gate_b[e];
    }
    __syncthreads();

    if (tid == 0) {
        float mx = lg[0];
#pragma unroll
        for (int e = 1; e < E_NUM; e++) mx = fmaxf(mx, lg[e]);
        float p[E_NUM];
#pragma unroll
        for (int e = 0; e < E_NUM; e++) p[e] = __expf(lg[e] - mx);
        // top-8 on unnormalized exp (softmax denom cancels in renormalization)
        float vals[K_TOP]; int sel[K_TOP]; float vsum = 0.f;
#pragma unroll
        for (int k = 0; k < K_TOP; k++) {
            int bj = 0; float bv = p[0];
            for (int e = 1; e < E_NUM; e++) if (p[e] > bv) { bv = p[e]; bj = e; }
            sel[k] = bj; vals[k] = bv; vsum += bv; p[bj] = -1.f;
        }
        const float inv = 1.f / vsum;
#pragma unroll
        for (int k = 0; k < K_TOP; k++) {
            const int e = sel[k];
            int slot = atomicAdd(&g_cnt[e], 1);
            if (slot < CAP) {
                g_tok[e * CAP + slot] = t;
                g_aid[e * CAP + slot] = (t << 3) + k;
                g_wgt[e * CAP + slot] = vals[k] * inv;
            }
        }
    }
}

// ---------------- GEMM1: h = silu(X Wg) * (X Wu), grouped by expert ----------------
// grid: (I/64, CAP/64, E), 256 threads, BM=BN=64, BK=16, 4x4 per thread (x2 for g/u)
__global__ __launch_bounds__(256, 3) void gemm1_kernel(const float* __restrict__ x,
                                                       const float* __restrict__ w_gate_up) {
    const int e = blockIdx.z;
    const int count = g_cnt[e];
    const int m0 = blockIdx.y * 64;
    if (m0 >= count) return;
    const int n0 = blockIdx.x * 64;

    __shared__ float As[16][64];
    __shared__ float Bg[16][64];
    __shared__ float Bu[16][64];
    __shared__ int toks[64];

    const int tid = threadIdx.x;
    if (tid < 64) {
        int s = m0 + tid; if (s >= count) s = count - 1;
        toks[tid] = g_tok[e * CAP + s];
    }
    __syncthreads();

    const int tx = tid & 15, ty = tid >> 4;
    const int ar = tid >> 2, ac = (tid & 3) << 2;       // A loader: row, 4-col seg
    const int bk = tid >> 4, bc = (tid & 15) << 2;      // B loader: k-row, 4-col seg
    const float* w1e = w_gate_up + (size_t)e * H_DIM * (2 * I_DIM);

    float accg[4][4], accu[4][4];
#pragma unroll
    for (int i = 0; i < 4; i++)
#pragma unroll
        for (int j = 0; j < 4; j++) { accg[i][j] = 0.f; accu[i][j] = 0.f; }

    for (int k0 = 0; k0 < H_DIM; k0 += 16) {
        const float4 av  = *(const float4*)(x + (size_t)toks[ar] * H_DIM + (k0 + ac));
        const float4 bgv = *(const float4*)(w1e + (size_t)(k0 + bk) * (2 * I_DIM) + (n0 + bc));
        const float4 buv = *(const float4*)(w1e + (size_t)(k0 + bk) * (2 * I_DIM) + (I_DIM + n0 + bc));
        __syncthreads();
        As[ac + 0][ar] = av.x; As[ac + 1][ar] = av.y; As[ac + 2][ar] = av.z; As[ac + 3][ar] = av.w;
        *(float4*)&Bg[bk][bc] = bgv;
        *(float4*)&Bu[bk][bc] = buv;
        __syncthreads();
#pragma unroll
        for (int kk = 0; kk < 16; kk++) {
            const float4 a4 = *(const float4*)&As[kk][ty << 2];
            const float4 g4 = *(const float4*)&Bg[kk][tx << 2];
            const float4 u4 = *(const float4*)&Bu[kk][tx << 2];
            const float a_[4] = {a4.x, a4.y, a4.z, a4.w};
            const float g_[4] = {g4.x, g4.y, g4.z, g4.w};
            const float u_[4] = {u4.x, u4.y, u4.z, u4.w};
#pragma unroll
            for (int i = 0; i < 4; i++)
#pragma unroll
                for (int j = 0; j < 4; j++) {
                    accg[i][j] += a_[i] * g_[j];
                    accu[i][j] += a_[i] * u_[j];
                }
        }
    }

#pragma unroll
    for (int i = 0; i < 4; i++) {
        const int slot = m0 + (ty << 2) + i;
        float4 o;
        float g0 = accg[i][0], g1 = accg[i][1], g2 = accg[i][2], g3 = accg[i][3];
        o.x = (g0 / (1.f + __expf(-g0))) * accu[i][0];
        o.y = (g1 / (1.f + __expf(-g1))) * accu[i][1];
        o.z = (g2 / (1.f + __expf(-g2))) * accu[i][2];
        o.w = (g3 / (1.f + __expf(-g3))) * accu[i][3];
        *(float4*)(g_h + ((size_t)e * CAP + slot) * I_DIM + n0 + (tx << 2)) = o;
    }
}

// ---------------- GEMM2: y[a] = (h Wd) * w, grouped by expert ----------------
// grid: (H/64, CAP/64, E), 256 threads, BM=BN=64, BK=16, 4x4 per thread
__global__ __launch_bounds__(256, 3) void gemm2_kernel(const float* __restrict__ w_down) {
    const int e = blockIdx.z;
    const int count = g_cnt[e];
    const int m0 = blockIdx.y * 64;
    if (m0 >= count) return;
    const int n0 = blockIdx.x * 64;

    __shared__ float As[16][64];
    __shared__ float Bs[16][64];

    const int tid = threadIdx.x;
    const int tx = tid & 15, ty = tid >> 4;
    const int ar = tid >> 2, ac = (tid & 3) << 2;
    const int bk = tid >> 4, bc = (tid & 15) << 2;

    const float* Ae = g_h + (size_t)e * CAP * I_DIM;
    const float* w2e = w_down + (size_t)e * I_DIM * H_DIM;

    float acc[4][4];
#pragma unroll
    for (int i = 0; i < 4; i++)
#pragma unroll
        for (int j = 0; j < 4; j++) acc[i][j] = 0.f;

    for (int k0 = 0; k0 < I_DIM; k0 += 16) {
        const float4 av = *(const float4*)(Ae + (size_t)(m0 + ar) * I_DIM + (k0 + ac));
        const float4 bv = *(const float4*)(w2e + (size_t)(k0 + bk) * H_DIM + (n0 + bc));
        __syncthreads();
        As[ac + 0][ar] = av.x; As[ac + 1][ar] = av.y; As[ac + 2][ar] = av.z; As[ac + 3][ar] = av.w;
        *(float4*)&Bs[bk][bc] = bv;
        __syncthreads();
#pragma unroll
        for (int kk = 0; kk < 16; kk++) {
            const float4 a4 = *(const float4*)&As[kk][ty << 2];
            const float4 b4 = *(const float4*)&Bs[kk][tx << 2];
            const float a_[4] = {a4.x, a4.y, a4.z, a4.w};
            const float b_[4] = {b4.x, b4.y, b4.z, b4.w};
#pragma unroll
            for (int i = 0; i < 4; i++)
#pragma unroll
                for (int j = 0; j < 4; j++) acc[i][j] += a_[i] * b_[j];
        }
    }

#pragma unroll
    for (int i = 0; i < 4; i++) {
        const int slot = m0 + (ty << 2) + i;
        if (slot < count) {
            const int   a  = g_aid[e * CAP + slot];
            const float wv = g_wgt[e * CAP + slot];
            float4 o;
            o.x = acc[i][0] * wv; o.y = acc[i][1] * wv;
            o.z = acc[i][2] * wv; o.w = acc[i][3] * wv;
            *(float4*)(g_y + (size_t)a * H_DIM + n0 + (tx << 2)) = o;
        }
    }
}

// ---------------- combine: out[t] = sum_k y[t*8+k] ----------------
__global__ void combine_kernel(float* __restrict__ out) {
    const size_t i = (size_t)blockIdx.x * 256 + threadIdx.x;   // 0 .. T*H-1
    const int t = (int)(i >> 11);
    const int h = (int)(i & (H_DIM - 1));
    const float* yb = g_y + ((size_t)t * K_TOP) * H_DIM + h;
    float s = 0.f;
#pragma unroll
    for (int k = 0; k < K_TOP; k++) s += yb[(size_t)k * H_DIM];
    out[i] = s;
}

// ---------------- launch ----------------
extern "C" void kernel_launch(void* const* d_in, const int* in_sizes, int n_in,
                              void* d_out, int out_size) {
    const float* x  = (const float*)d_in[0];   // hidden_states [T,H]
    const float* gw = (const float*)d_in[1];   // gate_w [H,E]
    const float* gb = (const float*)d_in[2];   // gate_b [E]
    const float* w1 = (const float*)d_in[3];   // w_gate_up [E,H,2I]
    const float* w2 = (const float*)d_in[4];   // w_down [E,I,H]
    float* out = (float*)d_out;

    prep_kernel<<<256, 256>>>(gw);
    router_kernel<<<T_TOK, 256>>>(x, gb);
    dim3 g1(I_DIM / 64, CAP / 64, E_NUM);      // 12,16,32
    gemm1_kernel<<<g1, 256>>>(x, w1);
    dim3 g2(H_DIM / 64, CAP / 64, E_NUM);      // 32,16,32
    gemm2_kernel<<<g2, 256>>>(w2);
    combine_kernel<<<(T_TOK * H_DIM) / 256, 256>>>(out);
}

// round 2
// speedup vs baseline: 2.5836x; 2.5836x over previous
#include <cuda_runtime.h>
#include <cuda_bf16.h>
#include <math.h>
#include <stdint.h>

#define T_TOK 2048
#define H_DIM 2048
#define I_DIM 768
#define E_NUM 32
#define K_TOP 8
#define CAP   1024
#define A_TOTAL (T_TOK * K_TOP)
#define N1 (2 * I_DIM)          // 1536

// ---------------- device scratch ----------------
__device__ float g_gate_wT[E_NUM * H_DIM];
__device__ int   g_cnt[E_NUM];
__device__ int   g_tok[E_NUM * CAP];
__device__ int   g_aid[E_NUM * CAP];
__device__ float g_wgt[E_NUM * CAP];
__device__ float g_h1[(size_t)E_NUM * CAP * N1];               // 192 MB, gate|up pre-activation
__device__ unsigned short g_hh[(size_t)E_NUM * CAP * I_DIM];   // 48 MB, h hi (bf16 bits)
__device__ unsigned short g_hl[(size_t)E_NUM * CAP * I_DIM];   // 48 MB, h lo
__device__ float g_y[(size_t)A_TOTAL * H_DIM];                 // 128 MB

// ---------------- helpers ----------------
__device__ __forceinline__ void split_bf16(float x, unsigned short& h, unsigned short& l) {
    __nv_bfloat16 bh = __float2bfloat16_rn(x);
    h = *reinterpret_cast<unsigned short*>(&bh);
    float r = x - __bfloat162float(bh);
    __nv_bfloat16 bl = __float2bfloat16_rn(r);
    l = *reinterpret_cast<unsigned short*>(&bl);
}

__device__ __forceinline__ uint32_t smem_u32(const void* p) {
    return (uint32_t)__cvta_generic_to_shared(p);
}

__device__ __forceinline__ void ldsm4(uint32_t& r0, uint32_t& r1, uint32_t& r2, uint32_t& r3, uint32_t addr) {
    asm volatile("ldmatrix.sync.aligned.m8n8.x4.shared.b16 {%0,%1,%2,%3}, [%4];\n"
                 : "=r"(r0), "=r"(r1), "=r"(r2), "=r"(r3) : "r"(addr));
}
__device__ __forceinline__ void ldsm4t(uint32_t& r0, uint32_t& r1, uint32_t& r2, uint32_t& r3, uint32_t addr) {
    asm volatile("ldmatrix.sync.aligned.m8n8.x4.trans.shared.b16 {%0,%1,%2,%3}, [%4];\n"
                 : "=r"(r0), "=r"(r1), "=r"(r2), "=r"(r3) : "r"(addr));
}
__device__ __forceinline__ void mma16816(float* c, const uint32_t* a, const uint32_t* b) {
    asm volatile("mma.sync.aligned.m16n8k16.row.col.f32.bf16.bf16.f32 "
                 "{%0,%1,%2,%3}, {%4,%5,%6,%7}, {%8,%9}, {%0,%1,%2,%3};\n"
                 : "+f"(c[0]), "+f"(c[1]), "+f"(c[2]), "+f"(c[3])
                 : "r"(a[0]), "r"(a[1]), "r"(a[2]), "r"(a[3]), "r"(b[0]), "r"(b[1]));
}

// ---------------- prep ----------------
__global__ void prep_kernel(const float* __restrict__ gate_w) {
    int i = blockIdx.x * 256 + threadIdx.x;
    if (i < E_NUM * H_DIM) {
        int e = i >> 11;
        int h = i & (H_DIM - 1);
        g_gate_wT[i] = gate_w[h * E_NUM + e];
    }
    if (i < E_NUM) g_cnt[i] = 0;
}

// ---------------- router ----------------
__global__ __launch_bounds__(256) void router_kernel(const float* __restrict__ x,
                                                     const float* __restrict__ gate_b) {
    __shared__ float xs[H_DIM];
    __shared__ float lg[E_NUM];
    const int t = blockIdx.x;
    const int tid = threadIdx.x;

    const float4* xr = (const float4*)(x + (size_t)t * H_DIM);
    for (int i = tid; i < H_DIM / 4; i += 256) ((float4*)xs)[i] = xr[i];
    __syncthreads();

    const int w = tid >> 5, lane = tid & 31;
#pragma unroll
    for (int ee = 0; ee < 4; ee++) {
        const int e = (w << 2) + ee;
        const float* gw = g_gate_wT + (size_t)e * H_DIM;
        float s = 0.f;
        for (int h = lane; h < H_DIM; h += 32) s += xs[h] * gw[h];
#pragma unroll
        for (int off = 16; off; off >>= 1) s += __shfl_xor_sync(0xffffffffu, s, off);
        if (lane == 0) lg[e] = s + gate_b[e];
    }
    __syncthreads();

    if (tid == 0) {
        float mx = lg[0];
#pragma unroll
        for (int e = 1; e < E_NUM; e++) mx = fmaxf(mx, lg[e]);
        float p[E_NUM];
#pragma unroll
        for (int e = 0; e < E_NUM; e++) p[e] = __expf(lg[e] - mx);
        float vals[K_TOP]; int sel[K_TOP]; float vsum = 0.f;
#pragma unroll
        for (int k = 0; k < K_TOP; k++) {
            int bj = 0; float bv = p[0];
            for (int e = 1; e < E_NUM; e++) if (p[e] > bv) { bv = p[e]; bj = e; }
            sel[k] = bj; vals[k] = bv; vsum += bv; p[bj] = -1.f;
        }
        const float inv = 1.f / vsum;
#pragma unroll
        for (int k = 0; k < K_TOP; k++) {
            const int e = sel[k];
            int slot = atomicAdd(&g_cnt[e], 1);
            if (slot < CAP) {
                g_tok[e * CAP + slot] = t;
                g_aid[e * CAP + slot] = (t << 3) + k;
                g_wgt[e * CAP + slot] = vals[k] * inv;
            }
        }
    }
}

// ---------------- bf16x3 tensor-core grouped GEMM ----------------
// MODE 0: A = gathered x rows (fp32, split on the fly), out = g_h1 (fp32, [CAP][NDIM])
// MODE 1: A = g_hh/g_hl (pre-split bf16),               out = g_y[aid] * wgt
template<int KDIM, int NDIM, int MODE>
__global__ __launch_bounds__(256) void gemm_mma(const float* __restrict__ Xin,
                                                const float* __restrict__ W) {
    const int e = blockIdx.z;
    const int count = g_cnt[e];
    const int m0 = blockIdx.y * 128;
    if (m0 >= count) return;
    const int n0 = blockIdx.x * 128;
    const int tid = threadIdx.x;

    __shared__ __align__(16) unsigned short As_hi[2][128][24];
    __shared__ __align__(16) unsigned short As_lo[2][128][24];
    __shared__ __align__(16) unsigned short Bs_hi[2][16][136];
    __shared__ __align__(16) unsigned short Bs_lo[2][16][136];
    __shared__ int toks[128];

    if (MODE == 0) {
        if (tid < 128) {
            int s = m0 + tid; if (s >= count) s = count - 1;
            toks[tid] = g_tok[e * CAP + s];
        }
        __syncthreads();
    }

    // ---- tile loaders ----
    const int arow = tid >> 1, aks = (tid & 1) * 8;     // A: 128 rows x 16 k
    const int bk = tid >> 4, bn = (tid & 15) * 8;       // B: 16 k x 128 n
    const float* Wb = W + (size_t)e * KDIM * NDIM + (size_t)bk * NDIM + n0 + bn;
    const float* Ab = nullptr;
    const unsigned short *Ah = nullptr, *Al = nullptr;
    if (MODE == 0) {
        Ab = Xin + (size_t)toks[arow] * H_DIM + aks;
    } else {
        size_t off = ((size_t)(e * CAP) + m0 + arow) * KDIM + aks;
        Ah = g_hh + off; Al = g_hl + off;
    }

    float ra[8], rb[8];
    uint4 rah, ral;

    auto loadA = [&](int k0) {
        if (MODE == 0) {
            float4 v0 = *(const float4*)(Ab + k0);
            float4 v1 = *(const float4*)(Ab + k0 + 4);
            ra[0]=v0.x; ra[1]=v0.y; ra[2]=v0.z; ra[3]=v0.w;
            ra[4]=v1.x; ra[5]=v1.y; ra[6]=v1.z; ra[7]=v1.w;
        } else {
            rah = *(const uint4*)(Ah + k0);
            ral = *(const uint4*)(Al + k0);
        }
    };
    auto loadB = [&](int k0) {
        const float* p = Wb + (size_t)k0 * NDIM;
        float4 v0 = *(const float4*)p;
        float4 v1 = *(const float4*)(p + 4);
        rb[0]=v0.x; rb[1]=v0.y; rb[2]=v0.z; rb[3]=v0.w;
        rb[4]=v1.x; rb[5]=v1.y; rb[6]=v1.z; rb[7]=v1.w;
    };
    auto storeA = [&](int b) {
        if (MODE == 0) {
            uint32_t h[4], l[4];
#pragma unroll
            for (int i = 0; i < 4; i++) {
                unsigned short h0, h1, l0, l1;
                split_bf16(ra[2*i],   h0, l0);
                split_bf16(ra[2*i+1], h1, l1);
                h[i] = (uint32_t)h0 | ((uint32_t)h1 << 16);
                l[i] = (uint32_t)l0 | ((uint32_t)l1 << 16);
            }
            *(uint4*)&As_hi[b][arow][aks] = make_uint4(h[0], h[1], h[2], h[3]);
            *(uint4*)&As_lo[b][arow][aks] = make_uint4(l[0], l[1], l[2], l[3]);
        } else {
            *(uint4*)&As_hi[b][arow][aks] = rah;
            *(uint4*)&As_lo[b][arow][aks] = ral;
        }
    };
    auto storeB = [&](int b) {
        uint32_t h[4], l[4];
#pragma unroll
        for (int i = 0; i < 4; i++) {
            unsigned short h0, h1, l0, l1;
            split_bf16(rb[2*i],   h0, l0);
            split_bf16(rb[2*i+1], h1, l1);
            h[i] = (uint32_t)h0 | ((uint32_t)h1 << 16);
            l[i] = (uint32_t)l0 | ((uint32_t)l1 << 16);
        }
        *(uint4*)&Bs_hi[b][bk][bn] = make_uint4(h[0], h[1], h[2], h[3]);
        *(uint4*)&Bs_lo[b][bk][bn] = make_uint4(l[0], l[1], l[2], l[3]);
    };

    // ---- fragment addressing ----
    const int lane = tid & 31, wid = tid >> 5;
    const int wm = (wid >> 2) * 64;   // 2 warps in M
    const int wn = (wid & 3) * 32;    // 4 warps in N
    const int rl = (lane & 7) + ((lane >> 3) & 1) * 8;   // row/k within 16
    const int ch = (lane >> 4) & 1;                      // 8-col half select

    const uint32_t aHiBase = smem_u32(&As_hi[0][0][0]);
    const uint32_t aLoBase = smem_u32(&As_lo[0][0][0]);
    const uint32_t bHiBase = smem_u32(&Bs_hi[0][0][0]);
    const uint32_t bLoBase = smem_u32(&Bs_lo[0][0][0]);
    uint32_t a_rel[4], b_rel[2];
#pragma unroll
    for (int mt = 0; mt < 4; mt++)
        a_rel[mt] = (uint32_t)(((wm + mt * 16 + rl) * 24 + ch * 8) * 2);
#pragma unroll
    for (int np = 0; np < 2; np++)
        b_rel[np] = (uint32_t)((rl * 136 + wn + np * 16 + ch * 8) * 2);

    float c[4][4][4];
#pragma unroll
    for (int i = 0; i < 4; i++)
#pragma unroll
        for (int j = 0; j < 4; j++)
#pragma unroll
            for (int q = 0; q < 4; q++) c[i][j][q] = 0.f;

    const int NK = KDIM / 16;
    loadA(0); loadB(0);
    storeA(0); storeB(0);
    __syncthreads();

    for (int ks = 0; ks < NK; ks++) {
        const int cur = ks & 1;
        if (ks + 1 < NK) { loadA((ks + 1) * 16); loadB((ks + 1) * 16); }

        const uint32_t ao = (uint32_t)(cur * 128 * 24 * 2);
        const uint32_t bo = (uint32_t)(cur * 16 * 136 * 2);

        uint32_t Afh[4][4], Afl[4][4], Bfh[4][2], Bfl[4][2];
#pragma unroll
        for (int mt = 0; mt < 4; mt++) {
            ldsm4(Afh[mt][0], Afh[mt][1], Afh[mt][2], Afh[mt][3], aHiBase + ao + a_rel[mt]);
            ldsm4(Afl[mt][0], Afl[mt][1], Afl[mt][2], Afl[mt][3], aLoBase + ao + a_rel[mt]);
        }
#pragma unroll
        for (int np = 0; np < 2; np++) {
            uint32_t r0, r1, r2, r3;
            ldsm4t(r0, r1, r2, r3, bHiBase + bo + b_rel[np]);
            Bfh[2*np][0] = r0; Bfh[2*np][1] = r1; Bfh[2*np+1][0] = r2; Bfh[2*np+1][1] = r3;
            ldsm4t(r0, r1, r2, r3, bLoBase + bo + b_rel[np]);
            Bfl[2*np][0] = r0; Bfl[2*np][1] = r1; Bfl[2*np+1][0] = r2; Bfl[2*np+1][1] = r3;
        }
#pragma unroll
        for (int mt = 0; mt < 4; mt++)
#pragma unroll
            for (int nt = 0; nt < 4; nt++) {
                mma16816(c[mt][nt], Afh[mt], Bfh[nt]);
                mma16816(c[mt][nt], Afh[mt], Bfl[nt]);
                mma16816(c[mt][nt], Afl[mt], Bfh[nt]);
            }

        __syncthreads();
        if (ks + 1 < NK) {
            storeA((ks + 1) & 1); storeB((ks + 1) & 1);
            __syncthreads();
        }
    }

    // ---- epilogue ----
    if (MODE == 0) {
        float* op = g_h1 + ((size_t)(e * CAP + m0)) * NDIM + n0;
#pragma unroll
        for (int mt = 0; mt < 4; mt++) {
            const int r = wm + mt * 16 + (lane >> 2);
#pragma unroll
            for (int nt = 0; nt < 4; nt++) {
                const int cI = wn + nt * 8 + (lane & 3) * 2;
                float2 v0; v0.x = c[mt][nt][0]; v0.y = c[mt][nt][1];
                float2 v1; v1.x = c[mt][nt][2]; v1.y = c[mt][nt][3];
                *(float2*)&op[(size_t)r * NDIM + cI] = v0;
                *(float2*)&op[(size_t)(r + 8) * NDIM + cI] = v1;
            }
        }
    } else {
#pragma unroll
        for (int mt = 0; mt < 4; mt++) {
            const int rbase = wm + mt * 16 + (lane >> 2);
#pragma unroll
            for (int half = 0; half < 2; half++) {
                const int slot = m0 + rbase + half * 8;
                if (slot < count) {
                    const float wv = g_wgt[e * CAP + slot];
                    const int aid = g_aid[e * CAP + slot];
                    float* yp = g_y + (size_t)aid * H_DIM + n0;
#pragma unroll
                    for (int nt = 0; nt < 4; nt++) {
                        const int cI = wn + nt * 8 + (lane & 3) * 2;
                        float2 v;
                        v.x = c[mt][nt][2 * half]     * wv;
                        v.y = c[mt][nt][2 * half + 1] * wv;
                        *(float2*)&yp[cI] = v;
                    }
                }
            }
        }
    }
}

// ---------------- silu + split to bf16 hi/lo ----------------
__global__ void silu_split_kernel() {
    const int col = blockIdx.x * 256 + threadIdx.x;   // 0..767 (grid.x = 3)
    const int slot = blockIdx.y;
    const int e = blockIdx.z;
    const int count = g_cnt[e];
    const size_t o = (size_t)(e * CAP + slot) * I_DIM + col;
    float h = 0.f;
    if (slot < count) {
        const float* p = g_h1 + (size_t)(e * CAP + slot) * N1;
        const float g = p[col];
        const float u = p[col + I_DIM];
        h = (g / (1.f + __expf(-g))) * u;
    }
    unsigned short hh, hl;
    split_bf16(h, hh, hl);
    g_hh[o] = hh;
    g_hl[o] = hl;
}

// ---------------- combine ----------------
__global__ void combine_kernel(float* __restrict__ out) {
    const size_t i = (size_t)blockIdx.x * 256 + threadIdx.x;
    const int t = (int)(i >> 11);
    const int h = (int)(i & (H_DIM - 1));
    const float* yb = g_y + ((size_t)t * K_TOP) * H_DIM + h;
    float s = 0.f;
#pragma unroll
    for (int k = 0; k < K_TOP; k++) s += yb[(size_t)k * H_DIM];
    out[i] = s;
}

// ---------------- launch ----------------
extern "C" void kernel_launch(void* const* d_in, const int* in_sizes, int n_in,
                              void* d_out, int out_size) {
    const float* x  = (const float*)d_in[0];
    const float* gw = (const float*)d_in[1];
    const float* gb = (const float*)d_in[2];
    const float* w1 = (const float*)d_in[3];
    const float* w2 = (const float*)d_in[4];
    float* out = (float*)d_out;

    prep_kernel<<<256, 256>>>(gw);
    router_kernel<<<T_TOK, 256>>>(x, gb);

    dim3 g1(N1 / 128, CAP / 128, E_NUM);        // 12, 8, 32
    gemm_mma<H_DIM, N1, 0><<<g1, 256>>>(x, w1);

    silu_split_kernel<<<dim3(3, CAP, E_NUM), 256>>>();

    dim3 g2(H_DIM / 128, CAP / 128, E_NUM);     // 16, 8, 32
    gemm_mma<I_DIM, H_DIM, 1><<<g2, 256>>>(x, w2);

    combine_kernel<<<(T_TOK * H_DIM) / 256, 256>>>(out);
}